// round 17
// baseline (speedup 1.0000x reference)
#include <cuda_runtime.h>
#include <stdint.h>
#include <math.h>

#define SEQ_L     200
#define EPS2      (1e-8f * 1e-8f)
#define VOCAB_MAX 100352
#define VROWS     32
#define NSEC      8
#define NT        128

// Per-vocab precomputed table: (a0, a0*wd0, a1, a1*wd1)
__device__ float4 g_vtab[VOCAB_MAX];
// Monotonic per-section tile-completion counters (never reset; replay-safe).
__device__ unsigned int g_sec[NSEC];
// Per-consumer-block execution counters: value before increment == replay index.
__device__ unsigned int g_blk_epoch[16384];

__device__ __forceinline__ uint32_t smem_u32(const void* p) {
    return (uint32_t)__cvta_generic_to_shared(p);
}

__device__ __forceinline__ void mbar_wait(uint32_t mb, uint32_t par) {
    uint32_t done;
    do {
        asm volatile(
            "{\n\t.reg .pred p;\n\t"
            "mbarrier.try_wait.parity.acquire.cta.shared::cta.b64 p, [%1], %2;\n\t"
            "selp.b32 %0, 1, 0, p;\n\t}"
            : "=r"(done) : "r"(mb), "r"(par) : "memory");
    } while (!done);
}

__device__ __forceinline__ void tma_tile(uint32_t mb, const float4* dst,
                                         const float* emb, int r0, int nrows) {
    const unsigned int nbytes = (unsigned int)nrows * 400u;
    asm volatile("mbarrier.arrive.expect_tx.shared.b64 _, [%0], %1;"
                 :: "r"(mb), "r"(nbytes) : "memory");
    asm volatile("cp.async.bulk.shared::cta.global.mbarrier::complete_tx::bytes "
                 "[%0], [%1], %2, [%3];"
                 :: "r"(smem_u32(dst)), "l"(emb + (size_t)r0 * 100),
                    "r"(nbytes), "r"(mb) : "memory");
}

__device__ __forceinline__ unsigned int ld_acq(const unsigned int* p) {
    unsigned int v;
    asm volatile("ld.acquire.gpu.global.u32 %0, [%1];" : "=r"(v) : "l"(p) : "memory");
    return v;
}

__device__ __forceinline__ void red_release_add(unsigned int* p, unsigned int v) {
    asm volatile("red.release.gpu.global.add.u32 [%0], %1;" :: "l"(p), "r"(v) : "memory");
}

// Coherent (L2) float4 load — legal for data written earlier in this kernel.
__device__ __forceinline__ float4 ldcg4(const float4* p) {
    float4 v;
    asm volatile("ld.global.cg.v4.f32 {%0,%1,%2,%3}, [%4];"
                 : "=f"(v.x), "=f"(v.y), "=f"(v.z), "=f"(v.w) : "l"(p) : "memory");
    return v;
}

__global__ __launch_bounds__(NT, 8)
void binclf_fused(const int*   __restrict__ word_idxs,   // [B, 200]
                  const float* __restrict__ emb_table,   // [vocab, 100]
                  const float* __restrict__ weights,     // [100]
                  const float* __restrict__ attend_u,    // [100] chunk-major
                  float*       __restrict__ out,         // [B]
                  int B, int vocab, int nprod)
{
    const int t      = threadIdx.x;
    const int lane   = t & 31;
    const int w5     = t >> 5;
    const int ntiles = (vocab + VROWS - 1) / VROWS;

    if ((int)blockIdx.x < nprod) {
        // ================= PRODUCER: stream table tiles, publish sections ====
        __shared__ float4 sv[2][VROWS * 25];   // 2 x 12800 B
        __shared__ float4 su[25];
        __shared__ float4 sw[25];
        __shared__ __align__(8) unsigned long long mbar[2];

        const int pid = blockIdx.x;

        if (t < 25)                 su[t]      = ((const float4*)attend_u)[t];
        else if (t >= 32 && t < 57) sw[t - 32] = ((const float4*)weights)[t - 32];

        const uint32_t mb0 = smem_u32(&mbar[0]);
        const uint32_t mb1 = smem_u32(&mbar[1]);
        if (t == 0) {
            asm volatile("mbarrier.init.shared.b64 [%0], 1;" :: "r"(mb0) : "memory");
            asm volatile("mbarrier.init.shared.b64 [%0], 1;" :: "r"(mb1) : "memory");
        }
        __syncthreads();

        if (pid < ntiles && t == 0) {
            const int r0 = pid * VROWS;
            tma_tile(mb0, sv[0], emb_table, r0, min(VROWS, vocab - r0));
        }

        uint32_t ph[2] = {0, 0};
        int i = 0;
        for (int tile = pid; tile < ntiles; tile += nprod, i++) {
            const int buf = i & 1;
            const int ntile = tile + nprod;
            if (ntile < ntiles && t == 0) {
                const int r0 = ntile * VROWS;
                tma_tile(buf ? mb0 : mb1, sv[buf ^ 1], emb_table, r0,
                         min(VROWS, vocab - r0));
            }
            mbar_wait(buf ? mb1 : mb0, ph[buf]);
            ph[buf] ^= 1;

            // 64 tasks: t<32 -> chunk 0 rows, t in [32,64) -> chunk 1 rows.
            const int r0    = tile * VROWS;
            const int nrows = min(VROWS, vocab - r0);
            const int c     = (t >> 5) & 1;
            const int row   = t & 31;
            if (t < 64 && row < nrows) {
                const float4* vp = sv[buf] + row * 25 + (c ? 13 : 0);
                const float4* up = su + (c ? 13 : 0);
                const float4* wp = sw + (c ? 13 : 0);

                float s = 0.f, d = 0.f, wd = 0.f, uu = 0.f;
                #pragma unroll
                for (int j = 0; j < 12; j++) {
                    const float4 v = vp[j];
                    const float4 u = up[j];     // warp-uniform broadcast
                    const float4 q = wp[j];
                    s  = fmaf(v.x, v.x, fmaf(v.y, v.y, fmaf(v.z, v.z, fmaf(v.w, v.w, s))));
                    d  = fmaf(v.x, u.x, fmaf(v.y, u.y, fmaf(v.z, u.z, fmaf(v.w, u.w, d))));
                    wd = fmaf(v.x, q.x, fmaf(v.y, q.y, fmaf(v.z, q.z, fmaf(v.w, q.w, wd))));
                    uu = fmaf(u.x, u.x, fmaf(u.y, u.y, fmaf(u.z, u.z, fmaf(u.w, u.w, uu))));
                }
                // Boundary float4 #12: x,y -> chunk 0; z,w -> chunk 1.
                const float4 vb = sv[buf][row * 25 + 12];
                const float4 ub = su[12];
                const float4 qb = sw[12];
                const float ex = c ? vb.z : vb.x,  ey = c ? vb.w : vb.y;
                const float ux = c ? ub.z : ub.x,  uy = c ? ub.w : ub.y;
                const float wx = c ? qb.z : qb.x,  wy = c ? qb.w : qb.y;
                s  = fmaf(ex, ex, fmaf(ey, ey, s));
                d  = fmaf(ex, ux, fmaf(ey, uy, d));
                wd = fmaf(ex, wx, fmaf(ey, wy, wd));
                uu = fmaf(ux, ux, fmaf(uy, uy, uu));

                const float a = __expf(d * rsqrtf(fmaxf(s, EPS2))
                                         * rsqrtf(fmaxf(uu, EPS2)));
                float2* dst = (float2*)((float*)&g_vtab[r0 + row] + 2 * c);
                *dst = make_float2(a, a * wd);
            }
            __threadfence();
            __syncthreads();   // all STGs fenced + buffer consumed
            if (t == 0) {
                int s = 0;
                while (s < NSEC - 1 &&
                       tile >= (int)(((long long)(s + 1) * ntiles) / NSEC)) s++;
                red_release_add(&g_sec[s], 1u);
            }
        }
    } else {
        // ================= CONSUMER: 2 batch rows per block, gated gathers ===
        __shared__ float4 spart[4];
        __shared__ unsigned int sr;

        const int cbid = blockIdx.x - nprod;
        const int b    = cbid * 2 + (w5 >> 1);
        const int sub  = w5 & 1;

        // Preload this warp's 100 word indices (independent of the table).
        int4 idx4 = make_int4(-1, -1, -1, -1);
        if (b < B && lane < 25)
            idx4 = __ldg((const int4*)(word_idxs + (size_t)b * SEQ_L + sub * 100) + lane);

        if (t == 0) sr = atomicAdd(&g_blk_epoch[cbid], 1u);   // replay index
        __syncthreads();
        const unsigned int r = sr;

        float A0 = 0.f, P0 = 0.f, A1 = 0.f, P1 = 0.f;
        #pragma unroll 1
        for (int s = 0; s < NSEC; s++) {
            const int blo = (int)(((long long)s * ntiles) / NSEC);
            const int bhi = (int)(((long long)(s + 1) * ntiles) / NSEC);

            // One spinner per block; bar.sync propagates the acquire.
            if (t == 0) {
                const unsigned int target = (r + 1) * (unsigned int)(bhi - blo);
                while (ld_acq(&g_sec[s]) < target) __nanosleep(64);
            }
            __syncthreads();

            if (b < B) {
                const int lo = blo * VROWS;
                const int hi = min(bhi * VROWS, vocab);
                #define G1(ix)                                              \
                    if ((ix) >= lo && (ix) < hi) {                          \
                        const float4 v = ldcg4(&g_vtab[(ix)]);              \
                        A0 += v.x; P0 += v.y; A1 += v.z; P1 += v.w;         \
                    }
                G1(idx4.x) G1(idx4.y) G1(idx4.z) G1(idx4.w)
                #undef G1
            }
        }

        if (b < B) {
            #pragma unroll
            for (int o = 16; o > 0; o >>= 1) {
                A0 += __shfl_xor_sync(0xffffffffu, A0, o);
                P0 += __shfl_xor_sync(0xffffffffu, P0, o);
                A1 += __shfl_xor_sync(0xffffffffu, A1, o);
                P1 += __shfl_xor_sync(0xffffffffu, P1, o);
            }
        }

        if (lane == 0) spart[w5] = make_float4(A0, P0, A1, P1);
        __syncthreads();

        if (t < 2) {
            const int bb = cbid * 2 + t;
            if (bb < B) {
                const float4 x = spart[2 * t];
                const float4 y = spart[2 * t + 1];
                out[bb] = (x.y + y.y) / (x.x + y.x) + (x.w + y.w) / (x.z + y.z);
            }
        }
    }
}

extern "C" void kernel_launch(void* const* d_in, const int* in_sizes, int n_in,
                              void* d_out, int out_size)
{
    const int*   word_idxs = (const int*)  d_in[0];  // [B, 200] int32
    const float* emb_table = (const float*)d_in[1];  // [vocab, 100] f32
    const float* weights   = (const float*)d_in[2];  // [100, 1] f32
    const float* attend_u  = (const float*)d_in[3];  // [2, 50] f32
    float*       out       = (float*)d_out;          // [B] f32

    const int B     = in_sizes[0] / SEQ_L;
    const int vocab = in_sizes[1] / 100;

    const int ntiles = (vocab + VROWS - 1) / VROWS;
    int dev = 0, sms = 148;
    cudaGetDevice(&dev);
    cudaDeviceGetAttribute(&sms, cudaDevAttrMultiProcessorCount, dev);

    int nprod = 2 * sms;                 // producers: guaranteed wave-1 resident
    if (nprod > ntiles) nprod = ntiles;
    const int ncons = (B + 1) / 2;       // 2 batch rows per consumer block

    cudaFuncSetAttribute(binclf_fused,
                         cudaFuncAttributePreferredSharedMemoryCarveout, 100);
    binclf_fused<<<nprod + ncons, NT>>>(word_idxs, emb_table, weights, attend_u,
                                        out, B, vocab, nprod);
}